// round 10
// baseline (speedup 1.0000x reference)
#include <cuda_runtime.h>

// sLSTM: B=256, T=512, D=8, H=120, L=4, NH=8, HD=15
// Layer-pipelined dual scan streams (R10):
//  128 CTAs x 256 threads. Warp group A (0-3) scans layer 2*pass, group B
//  (4-7) scans layer 2*pass+1 one 16-step chunk behind, on the same SMSPs:
//  two independent issue streams per SMSP hide each other's serial latency.
//  Per phase p: B projects h_A chunk p-1 into its x stream (x_{l+1} =
//  x_l + proj(h_l)), bar.sync(B), scans it; A scans chunk p and projects
//  h_B chunk p-2 into A's x stream (input of the NEXT pass / final output).
//  Scan body per warp = R7 winner: 92 FFMA2 + ring h-exchange + 1-exp cell.

#define B_ 256
#define T_ 512
#define D_ 8
#define H_ 120
#define CH 16
#define NCH 32
#define HR 61              // ring row stride (ull)
#define HBAT 1953          // ring batch stride (32*61+1)
#define HGRP (2 * HBAT + 1)
#define XPS 4100           // x batch stride (floats)
#define LOG2E 1.4426950408889634f

typedef unsigned long long ull;

__device__ float g_last[B_ * D_];

__device__ __forceinline__ ull f2pack(float x, float y) {
    ull r; asm("mov.b64 %0, {%1, %2};" : "=l"(r) : "f"(x), "f"(y)); return r;
}
__device__ __forceinline__ void f2unpack(ull v, float& x, float& y) {
    asm("mov.b64 {%0, %1}, %2;" : "=f"(x), "=f"(y) : "l"(v));
}
__device__ __forceinline__ ull f2fma(ull a, ull b, ull c) {
    ull d; asm("fma.rn.f32x2 %0, %1, %2, %3;" : "=l"(d) : "l"(a), "l"(b), "l"(c));
    return d;
}
__device__ __forceinline__ ull f2add(ull a, ull b) {
    ull d; asm("add.rn.f32x2 %0, %1, %2;" : "=l"(d) : "l"(a), "l"(b));
    return d;
}
__device__ __forceinline__ float tanh_ap(float x) {
    float r; asm("tanh.approx.f32 %0, %1;" : "=f"(r) : "f"(x)); return r;
}
__device__ __forceinline__ float rcp_ap(float x) {
    float r; asm("rcp.approx.f32 %0, %1;" : "=f"(r) : "f"(x)); return r;
}
__device__ __forceinline__ float ex2_ap(float x) {
    float r; asm("ex2.approx.f32 %0, %1;" : "=f"(r) : "f"(x)); return r;
}

// sLSTM cell. it/ft pre-scaled by log2e, ot pre-scaled by 0.5.
__device__ __forceinline__ float cellf(float it, float ft, float zt, float ot,
                                       float& c, float& nn, float& m) {
    float z  = tanh_ap(zt);
    float o  = fmaf(tanh_ap(ot), 0.5f, 0.5f);
    float b  = ft + m;
    float mn = fmaxf(it, b);
    float e  = ex2_ap(-fabsf(it - b));
    bool ag  = (it >= b);
    float ip = ag ? 1.f : e;
    float fp = ag ? e : 1.f;
    c  = fp * c  + ip * z;
    nn = fp * nn + ip;
    m  = mn;
    return o * c * rcp_ap(nn);
}

// shared layout (ull units):
//   hring [2 groups][2 bat][32 rows][61]   = 7814
//   wpT   [2][480]                          = 960   (paired Wp, per group)
//   bps   [2][8] floats                     = 8
//   xA    [2][XPS] floats                   = 4100  (A's stream: x0 -> x2 -> x4)
//   xB    [2][XPS] floats                   = 4100  (B's stream: x1 -> x3)
#define SM_HR  0
#define SM_WPT 7814
#define SM_BPS (SM_WPT + 960)
#define SM_XA  (SM_BPS + 8)
#define SM_XB  (SM_XA + 4100)
#define SM_TOT (SM_XB + 4100)
#define SMEM_BYTES (SM_TOT * 8 + 16)

__global__ void __launch_bounds__(256, 1) slstm_kernel(
    const float* __restrict__ X,
    const float* __restrict__ Wi, const float* __restrict__ Wf,
    const float* __restrict__ Wz, const float* __restrict__ Wo,
    const float* __restrict__ Ri, const float* __restrict__ Rf,
    const float* __restrict__ Rz, const float* __restrict__ Ro,
    const float* __restrict__ bi, const float* __restrict__ bf,
    const float* __restrict__ bz, const float* __restrict__ bo,
    const float* __restrict__ Wp, const float* __restrict__ bp)
{
    extern __shared__ ull sm[];
    ull* hring = sm + SM_HR;
    ull* wpT   = sm + SM_WPT;
    float* bps = (float*)(sm + SM_BPS);
    float* xA  = (float*)(sm + SM_XA);
    float* xB  = (float*)(sm + SM_XB);

    const int tid  = threadIdx.x;
    const int lane = tid & 31;
    const int wid  = tid >> 5;
    const bool isB = (wid >= 4);
    const int k    = wid & 3;            // head block (pairs k+4)
    const int half = (lane >> 4) & 1;    // batch within CTA
    const int e    = lane & 15;
    const bool act = (e < 15);
    const int ec   = act ? e : 14;
    const int slot = k * 15 + ec;        // 0..59 (pairs with +60)
    const int b0   = blockIdx.x * 2;
    const int gtid = tid & 127;          // id within group
    const int g    = isB ? 1 : 0;        // own ring group
    // projection task split: 32 tasks x 4 lanes
    const int ptask = gtid >> 2;
    const int ppart = gtid & 3;
    const int pbat  = ptask >> 4;
    const int ptl   = ptask & 15;

    // load input x0 into xA
    for (int idx = tid; idx < 2 * T_ * D_; idx += 256) {
        int bbi = idx >> 12;
        int i   = idx & 4095;
        xA[bbi * XPS + i] = X[(b0 + bbi) * (T_ * D_) + i];
    }

    #pragma unroll 1
    for (int pass = 0; pass < 2; pass++) {
        const int l = pass * 2 + g;      // my layer
        // ---- packed weights into registers (i/f scaled log2e, o scaled .5) ----
        ull rIv[15], rFv[15], rZv[15], rOv[15];
        ull wIv[8],  wFv[8],  wZv[8],  wOv[8];
        ull bIv, bFv, bZv, bOv;
        {
            const int j0 = slot, j1 = slot + 60;
            const float* wi = Wi + l * H_ * D_;
            const float* wf = Wf + l * H_ * D_;
            const float* wz = Wz + l * H_ * D_;
            const float* wo = Wo + l * H_ * D_;
            #pragma unroll
            for (int d = 0; d < 8; d++) {
                wIv[d] = f2pack(LOG2E * wi[j0 * 8 + d], LOG2E * wi[j1 * 8 + d]);
                wFv[d] = f2pack(LOG2E * wf[j0 * 8 + d], LOG2E * wf[j1 * 8 + d]);
                wZv[d] = f2pack(wz[j0 * 8 + d], wz[j1 * 8 + d]);
                wOv[d] = f2pack(0.5f * wo[j0 * 8 + d], 0.5f * wo[j1 * 8 + d]);
            }
            const float* ri = Ri + l * 8 * 225;
            const float* rf = Rf + l * 8 * 225;
            const float* rz = Rz + l * 8 * 225;
            const float* ro = Ro + l * 8 * 225;
            #pragma unroll
            for (int d = 0; d < 15; d++) {
                int i0 = k * 225 + d * 15 + ec;
                int i1 = (k + 4) * 225 + d * 15 + ec;
                rIv[d] = f2pack(LOG2E * ri[i0], LOG2E * ri[i1]);
                rFv[d] = f2pack(LOG2E * rf[i0], LOG2E * rf[i1]);
                rZv[d] = f2pack(rz[i0], rz[i1]);
                rOv[d] = f2pack(0.5f * ro[i0], 0.5f * ro[i1]);
            }
            bIv = f2pack(LOG2E * bi[l * H_ + j0], LOG2E * bi[l * H_ + j1]);
            bFv = f2pack(LOG2E * bf[l * H_ + j0], LOG2E * bf[l * H_ + j1]);
            bZv = f2pack(bz[l * H_ + j0], bz[l * H_ + j1]);
            bOv = f2pack(0.5f * bo[l * H_ + j0], 0.5f * bo[l * H_ + j1]);
        }
        // wpT[gg] = paired Wp of layer pass*2+gg ; bps likewise
        for (int idx = tid; idx < 960; idx += 256) {
            int gg = idx / 480, r = idx - gg * 480;
            int pp = r >> 3, d = r & 7;
            const float* wp = Wp + (pass * 2 + gg) * D_ * H_;
            wpT[idx] = f2pack(wp[d * H_ + pp], wp[d * H_ + 60 + pp]);
        }
        if (tid < 16) bps[tid] = bp[(pass * 2 + (tid >> 3)) * D_ + (tid & 7)];
        // zero both rings' "step -1" row (row 31)
        for (int idx = tid; idx < 2 * 2 * HR; idx += 256) {
            int gg = idx / (2 * HR), r2 = idx % (2 * HR);
            hring[gg * HGRP + (r2 / HR) * HBAT + 31 * HR + (r2 % HR)] = 0ull;
        }
        __syncthreads();

        float c0 = 0.f, c1 = 0.f, n0 = 0.f, n1 = 0.f, m0 = 0.f, m1 = 0.f;

        ull* __restrict__ myring = hring + g * HGRP + half * HBAT;
        const int hoff = k * 15;

        #pragma unroll 1
        for (int p = 0; p < NCH + 2; p++) {
            // ---------- projection ----------
            // B: project h_A chunk p-1 : xB(c) = xA(c) + proj_wpT0(hA(c))
            // A: project h_B chunk p-2 : xA(c) = xB(c) + proj_wpT1(hB(c))
            {
                const int c = isB ? (p - 1) : (p - 2);
                if (c >= 0 && c < NCH) {
                    const int t   = c * CH + ptl;
                    const int row = t & 31;
                    const int og  = isB ? 0 : 1;
                    const ull* __restrict__ hsr =
                        hring + og * HGRP + pbat * HBAT + row * HR + ppart * 15;
                    const ull* __restrict__ wv = wpT + og * 480 + ppart * 120;
                    ull acc[8];
                    #pragma unroll
                    for (int d = 0; d < 8; d++) acc[d] = 0ull;
                    #pragma unroll
                    for (int j = 0; j < 15; j++) {
                        ull hv = hsr[j];
                        #pragma unroll
                        for (int d = 0; d < 8; d++)
                            acc[d] = f2fma(hv, wv[j * 8 + d], acc[d]);
                    }
                    #pragma unroll
                    for (int off = 1; off <= 2; off <<= 1) {
                        #pragma unroll
                        for (int d = 0; d < 8; d++) {
                            ull o = __shfl_xor_sync(0xffffffffu, acc[d], off);
                            acc[d] = f2add(acc[d], o);
                        }
                    }
                    if (ppart == 0) {
                        const float* src = (isB ? xA : xB) + pbat * XPS + t * 8;
                        float*       dst = (isB ? xB : xA) + pbat * XPS + t * 8;
                        const float* bb  = bps + og * 8;
                        #pragma unroll
                        for (int d = 0; d < 8; d++) {
                            float lo, hi; f2unpack(acc[d], lo, hi);
                            dst[d] = src[d] + lo + hi + bb[d];
                        }
                    }
                }
            }
            // B group: its scan reads what its own group just projected
            if (isB) asm volatile("bar.sync 1, 128;" ::: "memory");
            // ---------- scan ----------
            {
                const int c = isB ? (p - 1) : p;
                if (c >= 0 && c < NCH) {
                    const float* __restrict__ xr0 =
                        (isB ? xB : xA) + half * XPS + c * CH * 8;
                    #pragma unroll 2
                    for (int tt = 0; tt < CH; tt++) {
                        const int t = c * CH + tt;
                        const int row = t & 31;
                        const int prow = (t - 1) & 31;
                        ull aI = bIv, aF = bFv, aZ = bZv, aO = bOv;
                        const float* xr = xr0 + tt * 8;
                        #pragma unroll
                        for (int d = 0; d < 8; d++) {
                            float v = xr[d];
                            ull xv = f2pack(v, v);
                            aI = f2fma(xv, wIv[d], aI);
                            aF = f2fma(xv, wFv[d], aF);
                            aZ = f2fma(xv, wZv[d], aZ);
                            aO = f2fma(xv, wOv[d], aO);
                        }
                        const ull* __restrict__ hr = myring + prow * HR + hoff;
                        #pragma unroll
                        for (int d = 0; d < 15; d++) {
                            ull hv = hr[d];
                            aI = f2fma(hv, rIv[d], aI);
                            aF = f2fma(hv, rFv[d], aF);
                            aZ = f2fma(hv, rZv[d], aZ);
                            aO = f2fma(hv, rOv[d], aO);
                        }
                        float itx, ity, ftx, fty, ztx, zty, otx, oty;
                        f2unpack(aI, itx, ity); f2unpack(aF, ftx, fty);
                        f2unpack(aZ, ztx, zty); f2unpack(aO, otx, oty);
                        float h0 = cellf(itx, ftx, ztx, otx, c0, n0, m0);
                        float h1 = cellf(ity, fty, zty, oty, c1, n1, m1);
                        if (act)
                            myring[row * HR + slot] = f2pack(h0, h1);
                    }
                }
            }
            __syncthreads();
        }
    }

    // xA now holds x4 (layer-stack output)
    if (tid < 16) {
        int bbi = tid >> 3, d = tid & 7;
        g_last[(b0 + bbi) * D_ + d] = xA[bbi * XPS + 511 * 8 + d];
    }
}

__global__ void finalize_kernel(const float* __restrict__ gamma,
                                const float* __restrict__ beta,
                                const float* __restrict__ wfc,
                                const float* __restrict__ bfc,
                                float* __restrict__ out)
{
    __shared__ float red[8][8];
    __shared__ float smu[8], svar[8];
    int b = threadIdx.x;
    int lane = b & 31, w = b >> 5;
    float v[8];
    #pragma unroll
    for (int d = 0; d < 8; d++) v[d] = g_last[b * 8 + d];

    #pragma unroll
    for (int d = 0; d < 8; d++) {
        float sv = v[d];
        #pragma unroll
        for (int o = 16; o > 0; o >>= 1) sv += __shfl_xor_sync(0xffffffffu, sv, o);
        if (lane == 0) red[d][w] = sv;
    }
    __syncthreads();
    if (b < 8) {
        float sv = 0.f;
        #pragma unroll
        for (int kk = 0; kk < 8; kk++) sv += red[b][kk];
        smu[b] = sv * (1.f / 256.f);
    }
    __syncthreads();
    float mu[8];
    #pragma unroll
    for (int d = 0; d < 8; d++) mu[d] = smu[d];
    __syncthreads();

    #pragma unroll
    for (int d = 0; d < 8; d++) {
        float dv = v[d] - mu[d];
        float sv = dv * dv;
        #pragma unroll
        for (int o = 16; o > 0; o >>= 1) sv += __shfl_xor_sync(0xffffffffu, sv, o);
        if (lane == 0) red[d][w] = sv;
    }
    __syncthreads();
    if (b < 8) {
        float sv = 0.f;
        #pragma unroll
        for (int kk = 0; kk < 8; kk++) sv += red[b][kk];
        svar[b] = sv * (1.f / 256.f);
    }
    __syncthreads();

    float acc = bfc[0];
    #pragma unroll
    for (int d = 0; d < 8; d++) {
        float bn = (v[d] - mu[d]) * rsqrtf(svar[d] + 1e-5f) * gamma[d] + beta[d];
        acc = fmaf(bn, wfc[d], acc);
    }
    out[b] = 1.f / (1.f + expf(-acc));
}

extern "C" void kernel_launch(void* const* d_in, const int* in_sizes, int n_in,
                              void* d_out, int out_size) {
    const float* X    = (const float*)d_in[0];
    const float* Wi   = (const float*)d_in[1];
    const float* Wf   = (const float*)d_in[2];
    const float* Wz   = (const float*)d_in[3];
    const float* Wo   = (const float*)d_in[4];
    const float* Ri   = (const float*)d_in[5];
    const float* Rf   = (const float*)d_in[6];
    const float* Rz   = (const float*)d_in[7];
    const float* Ro   = (const float*)d_in[8];
    const float* bi   = (const float*)d_in[9];
    const float* bf   = (const float*)d_in[10];
    const float* bz   = (const float*)d_in[11];
    const float* bo   = (const float*)d_in[12];
    const float* Wp   = (const float*)d_in[13];
    const float* bp   = (const float*)d_in[14];
    const float* gam  = (const float*)d_in[15];
    const float* bet  = (const float*)d_in[16];
    const float* Wfc  = (const float*)d_in[17];
    const float* bfc  = (const float*)d_in[18];

    cudaFuncSetAttribute(slstm_kernel,
                         cudaFuncAttributeMaxDynamicSharedMemorySize, SMEM_BYTES);
    slstm_kernel<<<128, 256, SMEM_BYTES>>>(X, Wi, Wf, Wz, Wo, Ri, Rf, Rz, Ro,
                                           bi, bf, bz, bo, Wp, bp);
    finalize_kernel<<<1, 256>>>(gam, bet, Wfc, bfc, (float*)d_out);
}